// round 9
// baseline (speedup 1.0000x reference)
#include <cuda_runtime.h>
#include <cuda_bf16.h>
#include <cstdint>

#define B_   64
#define LQ_  1024
#define LK_  1024
#define D_   128
#define INV_T 0.08838834764831845f   // 1/sqrt(128)

// Scratch (static __device__, allocation-free):
__device__ __nv_bfloat16 g_Qhi[(size_t)B_ * LQ_ * D_];
__device__ __nv_bfloat16 g_Qlo[(size_t)B_ * LQ_ * D_];
__device__ __nv_bfloat16 g_Khi[(size_t)B_ * LK_ * D_];
__device__ __nv_bfloat16 g_Klo[(size_t)B_ * LK_ * D_];
__device__ __nv_bfloat16 g_Vt_hi[(size_t)B_ * D_ * LK_];   // [b][d][k]
__device__ __nv_bfloat16 g_Vt_lo[(size_t)B_ * D_ * LK_];

// ---------------------------------------------------------------------------
// helpers
// ---------------------------------------------------------------------------
__device__ __forceinline__ uint32_t smem_u32(const void* p) {
    uint32_t a;
    asm("{ .reg .u64 t; cvta.to.shared.u64 t, %1; cvt.u32.u64 %0, t; }" : "=r"(a) : "l"(p));
    return a;
}
__device__ __forceinline__ void ldsm_x4(uint32_t addr, uint32_t* r) {
    asm volatile("ldmatrix.sync.aligned.m8n8.x4.shared.b16 {%0,%1,%2,%3}, [%4];"
                 : "=r"(r[0]), "=r"(r[1]), "=r"(r[2]), "=r"(r[3]) : "r"(addr));
}
__device__ __forceinline__ void mma16816(float* d, const uint32_t* a, const uint32_t* b) {
    asm volatile("mma.sync.aligned.m16n8k16.row.col.f32.bf16.bf16.f32 "
                 "{%0,%1,%2,%3}, {%4,%5,%6,%7}, {%8,%9}, {%0,%1,%2,%3};"
                 : "+f"(d[0]), "+f"(d[1]), "+f"(d[2]), "+f"(d[3])
                 : "r"(a[0]), "r"(a[1]), "r"(a[2]), "r"(a[3]), "r"(b[0]), "r"(b[1]));
}
__device__ __forceinline__ void cpasync16(uint32_t dst, const void* src) {
    asm volatile("cp.async.cg.shared.global [%0], [%1], 16;" :: "r"(dst), "l"(src));
}
#define CP_COMMIT() asm volatile("cp.async.commit_group;" ::: "memory")
#define CP_WAIT(n)  asm volatile("cp.async.wait_group %0;" :: "n"(n) : "memory")

__device__ __forceinline__ uint32_t pk_bf2(__nv_bfloat16 a, __nv_bfloat16 b) {
    __nv_bfloat162 t(a, b);
    return *reinterpret_cast<uint32_t*>(&t);
}
__device__ __forceinline__ void split_f(float x, __nv_bfloat16& h, __nv_bfloat16& l) {
    h = __float2bfloat16(x);
    l = __float2bfloat16(x - __bfloat162float(h));
}

// ---- 64B-row tile layout (out_mma, 32-wide chunks) ----
#define T_AHI 0
#define T_ALO 8192
#define T_BHI 16384
#define T_BLO 24576
#define BUF_STRIDE 32768
#define SM_TOTAL 65536
__device__ __forceinline__ uint32_t swz(uint32_t r, uint32_t g) {
    return r * 64u + ((g ^ ((r >> 1) & 3u)) << 4);
}

// ---- 256B-row tile layout (fused kernel, full-D tiles) ----
__device__ __forceinline__ uint32_t off256(uint32_t r, uint32_t g) {
    return r * 256u + ((g ^ (r & 7u)) << 4);
}
// fused smem: QHI 0 | QLO 32K | KBUF0 64K..128K | KBUF1 128K..192K | MASKBITS 192K..208K
#define FS_QLO 32768u
#define FS_K0  65536u
#define FS_MB  196608
#define FS_TOTAL (196608 + 16384)

// fp32 stage layout inside a 64KB K buffer: row*512 + (col*4 ^ ((row&7)<<4))
__device__ __forceinline__ uint32_t stg_off(uint32_t row, uint32_t colByte) {
    return row * 512u + (colByte ^ ((row & 7u) << 4));
}

// ---------------------------------------------------------------------------
// MMA core over one 32-wide K chunk (64B-row tiles). Warp grid 2m x 4n; 64x32.
// ---------------------------------------------------------------------------
__device__ __forceinline__ void mma_chunk32(uint32_t sbuf, int lane, int wm, int wn,
                                            float acc[4][4][4])
{
    const uint32_t arow0 = (uint32_t)(wm * 64 + (lane & 15));
    const uint32_t nrow0 = (uint32_t)(wn * 32 + (lane & 7) + ((lane >> 4) << 3));
    const uint32_t ga = (uint32_t)(lane >> 4);
    const uint32_t gb = (uint32_t)((lane >> 3) & 1);

    #pragma unroll
    for (int ks = 0; ks < 2; ks++) {
        uint32_t bh[2][4], bl[2][4];
        #pragma unroll
        for (int nh = 0; nh < 2; nh++) {
            const uint32_t r = nrow0 + (uint32_t)(nh * 16);
            const uint32_t off = swz(r, (uint32_t)(ks * 2) + gb);
            ldsm_x4(sbuf + T_BHI + off, bh[nh]);
            ldsm_x4(sbuf + T_BLO + off, bl[nh]);
        }
        #pragma unroll
        for (int mt = 0; mt < 4; mt++) {
            const uint32_t r = arow0 + (uint32_t)(mt * 16);
            const uint32_t off = swz(r, (uint32_t)(ks * 2) + ga);
            uint32_t ah[4], al[4];
            ldsm_x4(sbuf + T_AHI + off, ah);
            ldsm_x4(sbuf + T_ALO + off, al);
            #pragma unroll
            for (int nt = 0; nt < 4; nt++) {
                const uint32_t* bhp = &bh[nt >> 1][(nt & 1) * 2];
                const uint32_t* blp = &bl[nt >> 1][(nt & 1) * 2];
                mma16816(acc[mt][nt], ah, bhp);
                mma16816(acc[mt][nt], ah, blp);
                mma16816(acc[mt][nt], al, bhp);
            }
        }
    }
}

// ---------------------------------------------------------------------------
// Prep: elementwise fp32 -> bf16 hi/lo split
// ---------------------------------------------------------------------------
__global__ __launch_bounds__(256) void split_kernel(
    const float* __restrict__ X, __nv_bfloat16* __restrict__ H, __nv_bfloat16* __restrict__ L)
{
    const size_t i = (size_t)blockIdx.x * 256 + threadIdx.x;
    float4 x = ((const float4*)X)[i];
    __nv_bfloat16 h0,h1,h2,h3,l0,l1,l2,l3;
    split_f(x.x,h0,l0); split_f(x.y,h1,l1); split_f(x.z,h2,l2); split_f(x.w,h3,l3);
    ((uint2*)H)[i] = make_uint2(pk_bf2(h0,h1), pk_bf2(h2,h3));
    ((uint2*)L)[i] = make_uint2(pk_bf2(l0,l1), pk_bf2(l2,l3));
}

// ---------------------------------------------------------------------------
// Prep: transpose + split V -> g_Vt_hi/lo [b][d][k]
// ---------------------------------------------------------------------------
__global__ __launch_bounds__(256) void vtrans_kernel(const float* __restrict__ V)
{
    __shared__ float tl[32][33];
    const int kt = blockIdx.x * 32, dt = blockIdx.y * 32, b = blockIdx.z;
    const int tx = threadIdx.x, ty = threadIdx.y;

    const float* Vb = V + ((size_t)b * LK_ + kt) * D_ + dt;
    #pragma unroll
    for (int j = 0; j < 4; j++) tl[ty + 8 * j][tx] = Vb[(size_t)(ty + 8 * j) * D_ + tx];
    __syncthreads();

    __nv_bfloat16* Hb = g_Vt_hi + ((size_t)b * D_ + dt) * LK_ + kt;
    __nv_bfloat16* Lb = g_Vt_lo + ((size_t)b * D_ + dt) * LK_ + kt;
    #pragma unroll
    for (int j = 0; j < 4; j++) {
        float f = tl[tx][ty + 8 * j];
        __nv_bfloat16 h, l; split_f(f, h, l);
        Hb[(size_t)(ty + 8 * j) * LK_ + tx] = h;
        Lb[(size_t)(ty + 8 * j) * LK_ + tx] = l;
    }
}

// ---------------------------------------------------------------------------
// FUSED scores + double softmax, one (b, 128-q) strip per CTA.
// Coalesced epilogue via smem staging; mask bits packed once in smem.
// ---------------------------------------------------------------------------
__global__ __launch_bounds__(512, 1) void fused_scores_softmax(
    const int* __restrict__ M, float* __restrict__ ATT, float* __restrict__ LA)
{
    extern __shared__ __align__(1024) char smem[];
    const uint32_t sb = smem_u32(smem);
    const int t = threadIdx.x, lane = t & 31;
    const int wid = t >> 5, wm = wid & 3, wn = wid >> 2;
    const int t4 = lane & 3, g8 = lane >> 2;

    const int qt = blockIdx.x, b = blockIdx.y;
    const size_t qrow0 = (size_t)b * LQ_ + (size_t)qt * 128;

    const __nv_bfloat16* Qh = g_Qhi + qrow0 * D_;
    const __nv_bfloat16* Ql = g_Qlo + qrow0 * D_;
    const __nv_bfloat16* Kh = g_Khi + (size_t)b * LK_ * D_;
    const __nv_bfloat16* Kl = g_Klo + (size_t)b * LK_ * D_;

    uint32_t* mb = (uint32_t*)(smem + FS_MB);   // [128 rows][32 words]

    // prologue: Q (resident) + K tile 0
    #pragma unroll
    for (int j = 0; j < 4; j++) {
        const uint32_t u = (uint32_t)t + 512u * j;
        const uint32_t row = u >> 4, g = u & 15;
        const uint32_t dst = off256(row, g);
        const size_t so = (size_t)row * D_ + g * 8;
        cpasync16(sb + dst,            Qh + so);
        cpasync16(sb + FS_QLO + dst,   Ql + so);
        cpasync16(sb + FS_K0 + dst,          Kh + so);
        cpasync16(sb + FS_K0 + 32768u + dst, Kl + so);
    }
    CP_COMMIT();

    float acc[2][4][4];
    #pragma unroll
    for (int i = 0; i < 2; i++)
        #pragma unroll
        for (int j = 0; j < 4; j++)
            #pragma unroll
            for (int v = 0; v < 4; v++) acc[i][j][v] = 0.f;
    float sU8[8], sM8[8];
    #pragma unroll
    for (int i = 0; i < 8; i++) { sU8[i] = 0.f; sM8[i] = 0.f; }

    // fragment lane addressing (verified in R8-fixed):
    const uint32_t brow0 = (uint32_t)(wn * 32 + (lane & 7) + ((lane >> 4) << 3));
    const uint32_t gbB   = (uint32_t)((lane >> 3) & 1);
    const uint32_t arow_ = (uint32_t)(lane & 15);
    const uint32_t gaA   = (uint32_t)(lane >> 4);

    for (int kt = 0; kt < 8; kt++) {
        if (kt < 7) {
            const uint32_t kb = sb + FS_K0 + (uint32_t)(((kt + 1) & 1) * 65536);
            const __nv_bfloat16* nh_ = Kh + (size_t)(kt + 1) * 128 * D_;
            const __nv_bfloat16* nl_ = Kl + (size_t)(kt + 1) * 128 * D_;
            #pragma unroll
            for (int j = 0; j < 4; j++) {
                const uint32_t u = (uint32_t)t + 512u * j;
                const uint32_t row = u >> 4, g = u & 15;
                const uint32_t dst = off256(row, g);
                const size_t so = (size_t)row * D_ + g * 8;
                cpasync16(kb + dst,          nh_ + so);
                cpasync16(kb + 32768u + dst, nl_ + so);
            }
            CP_COMMIT();
            CP_WAIT(1);
        } else {
            CP_WAIT(0);
        }
        __syncthreads();

        // ---- MMA on current K buffer ----
        const uint32_t kb = sb + FS_K0 + (uint32_t)((kt & 1) * 65536);
        #pragma unroll
        for (int ks = 0; ks < 8; ks++) {
            uint32_t bh[2][4], bl[2][4];
            #pragma unroll
            for (int nh = 0; nh < 2; nh++) {
                const uint32_t r = brow0 + (uint32_t)(nh * 16);
                const uint32_t off = off256(r, (uint32_t)(2 * ks) + gbB);
                ldsm_x4(kb + off, bh[nh]);
                ldsm_x4(kb + 32768u + off, bl[nh]);
            }
            #pragma unroll
            for (int mt = 0; mt < 2; mt++) {
                const uint32_t r = (uint32_t)(wm * 32 + mt * 16) + arow_;
                const uint32_t off = off256(r, (uint32_t)(2 * ks) + gaA);
                uint32_t ah[4], al[4];
                ldsm_x4(sb + off, ah);
                ldsm_x4(sb + FS_QLO + off, al);
                #pragma unroll
                for (int nt = 0; nt < 4; nt++) {
                    const uint32_t* bhp = &bh[nt >> 1][(nt & 1) * 2];
                    const uint32_t* blp = &bl[nt >> 1][(nt & 1) * 2];
                    mma16816(acc[mt][nt], ah, bhp);
                    mma16816(acc[mt][nt], ah, blp);
                    mma16816(acc[mt][nt], al, bhp);
                }
            }
        }
        __syncthreads();

        // ---- stage acc (fp32) into the just-consumed K buffer ----
        {
            char* stg = smem + FS_K0 + (size_t)((kt & 1) * 65536);
            #pragma unroll
            for (int mt = 0; mt < 2; mt++) {
                #pragma unroll
                for (int hf = 0; hf < 2; hf++) {
                    const uint32_t row = (uint32_t)(wm * 32 + mt * 16 + hf * 8 + g8);
                    #pragma unroll
                    for (int nt = 0; nt < 4; nt++) {
                        const uint32_t col = (uint32_t)(wn * 32 + nt * 8 + 2 * t4);
                        *(float2*)(stg + stg_off(row, col * 4)) =
                            make_float2(acc[mt][nt][hf * 2 + 0], acc[mt][nt][hf * 2 + 1]);
                    }
                }
            }
        }
        #pragma unroll
        for (int i = 0; i < 2; i++)
            #pragma unroll
            for (int j = 0; j < 4; j++)
                #pragma unroll
                for (int v = 0; v < 4; v++) acc[i][j][v] = 0.f;
        __syncthreads();

        // ---- coalesced epilogue: warp owns rows wid*8..wid*8+7 ----
        {
            const char* stg = smem + FS_K0 + (size_t)((kt & 1) * 65536);
            #pragma unroll
            for (int rl = 0; rl < 8; rl++) {
                const uint32_t row = (uint32_t)(wid * 8 + rl);
                float4 s = *(const float4*)(stg + stg_off(row, (uint32_t)lane * 16));
                s.x *= INV_T; s.y *= INV_T; s.z *= INV_T; s.w *= INV_T;
                const size_t gi = (qrow0 + row) * LK_ + (size_t)kt * 128 + lane * 4;
                const int4 m4 = *(const int4*)(M + gi);
                const float e0 = __expf(s.x), e1 = __expf(s.y),
                            e2 = __expf(s.z), e3 = __expf(s.w);
                sU8[rl] += (e0 + e1) + (e2 + e3);
                sM8[rl] += (m4.x ? 0.f : e0) + (m4.y ? 0.f : e1)
                         + (m4.z ? 0.f : e2) + (m4.w ? 0.f : e3);
                const uint32_t b0 = __ballot_sync(0xffffffffu, m4.x != 0);
                const uint32_t b1 = __ballot_sync(0xffffffffu, m4.y != 0);
                const uint32_t b2 = __ballot_sync(0xffffffffu, m4.z != 0);
                const uint32_t b3 = __ballot_sync(0xffffffffu, m4.w != 0);
                if (lane < 4)
                    mb[row * 32 + kt * 4 + lane] =
                        (lane == 0) ? b0 : (lane == 1) ? b1 : (lane == 2) ? b2 : b3;
                *(float4*)(LA + gi) = s;
            }
        }
        __syncthreads();   // release stage buffer before next iter's cp.async
    }

    // ---- finalize + pass 2: fully per-warp (each warp owns its 8 rows) ----
    #pragma unroll
    for (int rl = 0; rl < 8; rl++) {
        float u_ = sU8[rl], m_ = sM8[rl];
        #pragma unroll
        for (int o = 16; o > 0; o >>= 1) {
            u_ += __shfl_xor_sync(0xffffffffu, u_, o);
            m_ += __shfl_xor_sync(0xffffffffu, m_, o);
        }
        const float lse = __logf(u_);
        const float inv = 1.0f / m_;
        const uint32_t row = (uint32_t)(wid * 8 + rl);

        #pragma unroll
        for (int i = 0; i < 8; i++) {
            const size_t gi = (qrow0 + row) * LK_ + (size_t)i * 128 + lane * 4;
            const float4 s4 = *(const float4*)(LA + gi);
            const uint32_t w0 = mb[row * 32 + i * 4 + 0];
            const uint32_t w1 = mb[row * 32 + i * 4 + 1];
            const uint32_t w2 = mb[row * 32 + i * 4 + 2];
            const uint32_t w3 = mb[row * 32 + i * 4 + 3];
            float4 a4;
            a4.x = ((w0 >> lane) & 1u) ? 0.f : __expf(s4.x) * inv;
            a4.y = ((w1 >> lane) & 1u) ? 0.f : __expf(s4.y) * inv;
            a4.z = ((w2 >> lane) & 1u) ? 0.f : __expf(s4.z) * inv;
            a4.w = ((w3 >> lane) & 1u) ? 0.f : __expf(s4.w) * inv;
            *(float4*)(ATT + gi) = a4;
            *(float4*)(LA + gi) =
                make_float4(s4.x - lse, s4.y - lse, s4.z - lse, s4.w - lse);
        }
    }
}

// ---------------------------------------------------------------------------
// Kernel 3: O = A . V. A split inline (LDG prefetch), V via cp.async.
// ---------------------------------------------------------------------------
__device__ __forceinline__ void cp_tile_pair(
    uint32_t sbuf, uint32_t tHI, uint32_t tLO,
    const __nv_bfloat16* __restrict__ Hsrc, const __nv_bfloat16* __restrict__ Lsrc,
    int rowStride, int colOff, int t)
{
    #pragma unroll
    for (int j = 0; j < 2; j++) {
        const uint32_t u = (uint32_t)t + 256u * j;
        const uint32_t row = u >> 2, g = u & 3;
        const uint32_t dst = swz(row, g);
        const size_t so = (size_t)row * rowStride + colOff + g * 8;
        cpasync16(sbuf + tHI + dst, Hsrc + so);
        cpasync16(sbuf + tLO + dst, Lsrc + so);
    }
}
__device__ __forceinline__ void store_A_split(char* smem, uint32_t bufOff,
                                              const float4* a, int t)
{
    #pragma unroll
    for (int i = 0; i < 4; i++) {
        const uint32_t u = (uint32_t)t + 256u * i;
        const uint32_t row = u >> 3, f = u & 7;
        const uint32_t dst = bufOff + swz(row, f >> 1) + (f & 1) * 8;
        __nv_bfloat16 h0,h1,h2,h3,l0,l1,l2,l3;
        split_f(a[i].x,h0,l0); split_f(a[i].y,h1,l1);
        split_f(a[i].z,h2,l2); split_f(a[i].w,h3,l3);
        *(uint2*)(smem + T_AHI + dst) = make_uint2(pk_bf2(h0,h1), pk_bf2(h2,h3));
        *(uint2*)(smem + T_ALO + dst) = make_uint2(pk_bf2(l0,l1), pk_bf2(l2,l3));
    }
}
__device__ __forceinline__ void ldg_A(const float* __restrict__ Ab, int kc, int t, float4* a)
{
    #pragma unroll
    for (int i = 0; i < 4; i++) {
        const uint32_t u = (uint32_t)t + 256u * i;
        const uint32_t row = u >> 3, f = u & 7;
        a[i] = *(const float4*)(Ab + (size_t)row * LK_ + kc * 32 + f * 4);
    }
}

__global__ __launch_bounds__(256, 2) void out_mma(
    const float* __restrict__ A, float* __restrict__ O)
{
    extern __shared__ __align__(1024) char smem[];
    const uint32_t sb = smem_u32(smem);
    const int t = threadIdx.x, lane = t & 31, wid = t >> 5;
    const int wm = wid & 1, wn = wid >> 1;

    const int qt = blockIdx.x, b = blockIdx.y;
    const float* Ab = A + ((size_t)b * LQ_ + (size_t)qt * 128) * LK_;
    const __nv_bfloat16* Vh = g_Vt_hi + (size_t)b * D_ * LK_;
    const __nv_bfloat16* Vl = g_Vt_lo + (size_t)b * D_ * LK_;

    float acc[4][4][4];
    #pragma unroll
    for (int i = 0; i < 4; i++)
        #pragma unroll
        for (int j = 0; j < 4; j++)
            #pragma unroll
            for (int g = 0; g < 4; g++) acc[i][j][g] = 0.f;

    {
        float4 a0[4];
        ldg_A(Ab, 0, t, a0);
        cp_tile_pair(sb, T_BHI, T_BLO, Vh, Vl, LK_, 0, t);
        CP_COMMIT();
        store_A_split(smem, 0, a0, t);
        CP_WAIT(0);
        __syncthreads();
    }

    for (int kc = 0; kc < 32; kc++) {
        float4 an[4];
        const uint32_t nbOff = (uint32_t)(((kc + 1) & 1) * BUF_STRIDE);
        if (kc + 1 < 32) {
            ldg_A(Ab, kc + 1, t, an);
            cp_tile_pair(sb + nbOff, T_BHI, T_BLO, Vh, Vl, LK_, (kc + 1) * 32, t);
            CP_COMMIT();
        }
        mma_chunk32(sb + (uint32_t)((kc & 1) * BUF_STRIDE), lane, wm, wn, acc);
        if (kc + 1 < 32) {
            store_A_split(smem, nbOff, an, t);
            CP_WAIT(0);
        }
        __syncthreads();
    }

    const int g = lane >> 2, t4 = lane & 3;
    #pragma unroll
    for (int mt = 0; mt < 4; mt++) {
        const int m = wm * 64 + mt * 16 + g;
        float* Or0 = O + ((size_t)(b * LQ_ + qt * 128 + m)) * D_;
        float* Or1 = Or0 + 8 * D_;
        #pragma unroll
        for (int nt = 0; nt < 4; nt++) {
            const int c = wn * 32 + nt * 8 + 2 * t4;
            *(float2*)(Or0 + c) = make_float2(acc[mt][nt][0], acc[mt][nt][1]);
            *(float2*)(Or1 + c) = make_float2(acc[mt][nt][2], acc[mt][nt][3]);
        }
    }
}

// ---------------------------------------------------------------------------
// Launch. Inputs: q, k, v, attn_mask (int32).
// d_out layout: output | attn | log_attn.  Raw scores staged in log_attn.
// ---------------------------------------------------------------------------
extern "C" void kernel_launch(void* const* d_in, const int* in_sizes, int n_in,
                              void* d_out, int out_size)
{
    (void)in_sizes; (void)n_in; (void)out_size;
    const float* Q = (const float*)d_in[0];
    const float* K = (const float*)d_in[1];
    const float* V = (const float*)d_in[2];
    const int*   M = (const int*)d_in[3];

    float* O   = (float*)d_out;
    float* ATT = O   + (size_t)B_ * LQ_ * D_;
    float* LA  = ATT + (size_t)B_ * LQ_ * LK_;

    __nv_bfloat16 *qh, *ql, *kh, *kl;
    cudaGetSymbolAddress((void**)&qh, g_Qhi);
    cudaGetSymbolAddress((void**)&ql, g_Qlo);
    cudaGetSymbolAddress((void**)&kh, g_Khi);
    cudaGetSymbolAddress((void**)&kl, g_Klo);

    cudaFuncSetAttribute(fused_scores_softmax, cudaFuncAttributeMaxDynamicSharedMemorySize, FS_TOTAL);
    cudaFuncSetAttribute(out_mma, cudaFuncAttributeMaxDynamicSharedMemorySize, SM_TOTAL);

    const int n4 = B_ * LQ_ * D_ / 4;
    split_kernel<<<n4 / 256, 256>>>(Q, qh, ql);
    split_kernel<<<n4 / 256, 256>>>(K, kh, kl);
    vtrans_kernel<<<dim3(LK_ / 32, D_ / 32, B_), dim3(32, 8)>>>(V);
    fused_scores_softmax<<<dim3(LQ_ / 128, B_), 512, FS_TOTAL>>>(M, ATT, LA);
    out_mma<<<dim3(LQ_ / 128, B_), 256, SM_TOTAL>>>(ATT, O);
}

// round 10
// speedup vs baseline: 1.3927x; 1.3927x over previous
#include <cuda_runtime.h>
#include <cuda_bf16.h>
#include <cstdint>

#define B_   64
#define LQ_  1024
#define LK_  1024
#define D_   128
#define INV_T 0.08838834764831845f   // 1/sqrt(128)

// Scratch (static __device__, allocation-free):
__device__ __nv_bfloat16 g_Qhi[(size_t)B_ * LQ_ * D_];
__device__ __nv_bfloat16 g_Qlo[(size_t)B_ * LQ_ * D_];
__device__ __nv_bfloat16 g_Khi[(size_t)B_ * LK_ * D_];
__device__ __nv_bfloat16 g_Klo[(size_t)B_ * LK_ * D_];
__device__ __nv_bfloat16 g_Vt_hi[(size_t)B_ * D_ * LK_];   // [b][d][k]
__device__ __nv_bfloat16 g_Vt_lo[(size_t)B_ * D_ * LK_];

// ---------------------------------------------------------------------------
// helpers
// ---------------------------------------------------------------------------
__device__ __forceinline__ uint32_t smem_u32(const void* p) {
    uint32_t a;
    asm("{ .reg .u64 t; cvta.to.shared.u64 t, %1; cvt.u32.u64 %0, t; }" : "=r"(a) : "l"(p));
    return a;
}
__device__ __forceinline__ void ldsm_x4(uint32_t addr, uint32_t* r) {
    asm volatile("ldmatrix.sync.aligned.m8n8.x4.shared.b16 {%0,%1,%2,%3}, [%4];"
                 : "=r"(r[0]), "=r"(r[1]), "=r"(r[2]), "=r"(r[3]) : "r"(addr));
}
__device__ __forceinline__ void mma16816(float* d, const uint32_t* a, const uint32_t* b) {
    asm volatile("mma.sync.aligned.m16n8k16.row.col.f32.bf16.bf16.f32 "
                 "{%0,%1,%2,%3}, {%4,%5,%6,%7}, {%8,%9}, {%0,%1,%2,%3};"
                 : "+f"(d[0]), "+f"(d[1]), "+f"(d[2]), "+f"(d[3])
                 : "r"(a[0]), "r"(a[1]), "r"(a[2]), "r"(a[3]), "r"(b[0]), "r"(b[1]));
}
__device__ __forceinline__ void cpasync16(uint32_t dst, const void* src) {
    asm volatile("cp.async.cg.shared.global [%0], [%1], 16;" :: "r"(dst), "l"(src));
}
#define CP_COMMIT() asm volatile("cp.async.commit_group;" ::: "memory")
#define CP_WAIT(n)  asm volatile("cp.async.wait_group %0;" :: "n"(n) : "memory")

__device__ __forceinline__ uint32_t pk_bf2(__nv_bfloat16 a, __nv_bfloat16 b) {
    __nv_bfloat162 t(a, b);
    return *reinterpret_cast<uint32_t*>(&t);
}
__device__ __forceinline__ void split_f(float x, __nv_bfloat16& h, __nv_bfloat16& l) {
    h = __float2bfloat16(x);
    l = __float2bfloat16(x - __bfloat162float(h));
}

// ---- 64B-row tile layout; per-stage: AHI|ALO|BHI|BLO of 8KB each = 32KB ----
#define T_AHI 0
#define T_ALO 8192
#define T_BHI 16384
#define T_BLO 24576
#define BUF_STRIDE 32768
#define SM_TOTAL 98304           // 3 stages -> still 2 CTAs/SM (196KB < 228KB)
__device__ __forceinline__ uint32_t swz(uint32_t r, uint32_t g) {
    return r * 64u + ((g ^ ((r >> 1) & 3u)) << 4);
}

// ---------------------------------------------------------------------------
// MMA core over one 32-wide K chunk. Warp grid 2(m) x 4(n); warp tile 64x32.
// ---------------------------------------------------------------------------
__device__ __forceinline__ void mma_chunk32(uint32_t sbuf, int lane, int wm, int wn,
                                            float acc[4][4][4])
{
    const uint32_t arow0 = (uint32_t)(wm * 64 + (lane & 15));
    const uint32_t nrow0 = (uint32_t)(wn * 32 + (lane & 7) + ((lane >> 4) << 3));
    const uint32_t ga = (uint32_t)(lane >> 4);
    const uint32_t gb = (uint32_t)((lane >> 3) & 1);

    #pragma unroll
    for (int ks = 0; ks < 2; ks++) {
        uint32_t bh[2][4], bl[2][4];
        #pragma unroll
        for (int nh = 0; nh < 2; nh++) {
            const uint32_t r = nrow0 + (uint32_t)(nh * 16);
            const uint32_t off = swz(r, (uint32_t)(ks * 2) + gb);
            ldsm_x4(sbuf + T_BHI + off, bh[nh]);
            ldsm_x4(sbuf + T_BLO + off, bl[nh]);
        }
        #pragma unroll
        for (int mt = 0; mt < 4; mt++) {
            const uint32_t r = arow0 + (uint32_t)(mt * 16);
            const uint32_t off = swz(r, (uint32_t)(ks * 2) + ga);
            uint32_t ah[4], al[4];
            ldsm_x4(sbuf + T_AHI + off, ah);
            ldsm_x4(sbuf + T_ALO + off, al);
            #pragma unroll
            for (int nt = 0; nt < 4; nt++) {
                const uint32_t* bhp = &bh[nt >> 1][(nt & 1) * 2];
                const uint32_t* blp = &bl[nt >> 1][(nt & 1) * 2];
                mma16816(acc[mt][nt], ah, bhp);
                mma16816(acc[mt][nt], ah, blp);
                mma16816(acc[mt][nt], al, bhp);
            }
        }
    }
}

// ---------------------------------------------------------------------------
// Prep: fused Q/K fp32 -> bf16 hi/lo split (blockIdx.y selects tensor)
// ---------------------------------------------------------------------------
__global__ __launch_bounds__(256) void split2_kernel(
    const float* __restrict__ Q, const float* __restrict__ K,
    __nv_bfloat16* __restrict__ qh, __nv_bfloat16* __restrict__ ql,
    __nv_bfloat16* __restrict__ kh, __nv_bfloat16* __restrict__ kl)
{
    const float* X = blockIdx.y ? K : Q;
    __nv_bfloat16* H = blockIdx.y ? kh : qh;
    __nv_bfloat16* L = blockIdx.y ? kl : ql;
    const size_t i = (size_t)blockIdx.x * 256 + threadIdx.x;
    float4 x = ((const float4*)X)[i];
    __nv_bfloat16 h0,h1,h2,h3,l0,l1,l2,l3;
    split_f(x.x,h0,l0); split_f(x.y,h1,l1); split_f(x.z,h2,l2); split_f(x.w,h3,l3);
    ((uint2*)H)[i] = make_uint2(pk_bf2(h0,h1), pk_bf2(h2,h3));
    ((uint2*)L)[i] = make_uint2(pk_bf2(l0,l1), pk_bf2(l2,l3));
}

// ---------------------------------------------------------------------------
// Prep: transpose + split V -> g_Vt_hi/lo [b][d][k]
// ---------------------------------------------------------------------------
__global__ __launch_bounds__(256) void vtrans_kernel(const float* __restrict__ V)
{
    __shared__ float tl[32][33];
    const int kt = blockIdx.x * 32, dt = blockIdx.y * 32, b = blockIdx.z;
    const int tx = threadIdx.x, ty = threadIdx.y;

    const float* Vb = V + ((size_t)b * LK_ + kt) * D_ + dt;
    #pragma unroll
    for (int j = 0; j < 4; j++) tl[ty + 8 * j][tx] = Vb[(size_t)(ty + 8 * j) * D_ + tx];
    __syncthreads();

    __nv_bfloat16* Hb = g_Vt_hi + ((size_t)b * D_ + dt) * LK_ + kt;
    __nv_bfloat16* Lb = g_Vt_lo + ((size_t)b * D_ + dt) * LK_ + kt;
    #pragma unroll
    for (int j = 0; j < 4; j++) {
        float f = tl[tx][ty + 8 * j];
        __nv_bfloat16 h, l; split_f(f, h, l);
        Hb[(size_t)(ty + 8 * j) * LK_ + tx] = h;
        Lb[(size_t)(ty + 8 * j) * LK_ + tx] = l;
    }
}

// ---------------------------------------------------------------------------
// cp.async one 128x32 bf16 tile pair (hi+lo) into a stage buffer
// ---------------------------------------------------------------------------
__device__ __forceinline__ void cp_tile_pair(
    uint32_t sbuf, uint32_t tHI, uint32_t tLO,
    const __nv_bfloat16* __restrict__ Hsrc, const __nv_bfloat16* __restrict__ Lsrc,
    int rowStride, int colOff, int t)
{
    #pragma unroll
    for (int j = 0; j < 2; j++) {
        const uint32_t u = (uint32_t)t + 256u * j;
        const uint32_t row = u >> 2, g = u & 3;
        const uint32_t dst = swz(row, g);
        const size_t so = (size_t)row * rowStride + colOff + g * 8;
        cpasync16(sbuf + tHI + dst, Hsrc + so);
        cpasync16(sbuf + tLO + dst, Lsrc + so);
    }
}

// ---------------------------------------------------------------------------
// Kernel 1: scores. S = (Q . K^T) * INV_T into log_attn region.
// 3-stage cp.async pipeline (prefetch distance 2), one sync per chunk.
// ---------------------------------------------------------------------------
__global__ __launch_bounds__(256, 2) void scores_mma(float* __restrict__ S)
{
    extern __shared__ __align__(1024) char smem[];
    const uint32_t sb = smem_u32(smem);
    const int t = threadIdx.x, lane = t & 31, wid = t >> 5;
    const int wm = wid & 1, wn = wid >> 1;

    const int b = blockIdx.z, qt = blockIdx.y, kt = blockIdx.x;
    const __nv_bfloat16* Qh = g_Qhi + ((size_t)b * LQ_ + (size_t)qt * 128) * D_;
    const __nv_bfloat16* Ql = g_Qlo + ((size_t)b * LQ_ + (size_t)qt * 128) * D_;
    const __nv_bfloat16* Kh = g_Khi + ((size_t)b * LK_ + (size_t)kt * 128) * D_;
    const __nv_bfloat16* Kl = g_Klo + ((size_t)b * LK_ + (size_t)kt * 128) * D_;

    float acc[4][4][4];
    #pragma unroll
    for (int i = 0; i < 4; i++)
        #pragma unroll
        for (int j = 0; j < 4; j++)
            #pragma unroll
            for (int g = 0; g < 4; g++) acc[i][j][g] = 0.f;

    // prologue: chunks 0,1 -> stages 0,1
    cp_tile_pair(sb, T_AHI, T_ALO, Qh, Ql, D_, 0, t);
    cp_tile_pair(sb, T_BHI, T_BLO, Kh, Kl, D_, 0, t);
    CP_COMMIT();
    cp_tile_pair(sb + BUF_STRIDE, T_AHI, T_ALO, Qh, Ql, D_, 32, t);
    cp_tile_pair(sb + BUF_STRIDE, T_BHI, T_BLO, Kh, Kl, D_, 32, t);
    CP_COMMIT();

    #pragma unroll
    for (int dc = 0; dc < 4; dc++) {
        if (dc < 3) { CP_WAIT(1); } else { CP_WAIT(0); }
        __syncthreads();
        if (dc + 2 < 4) {
            const uint32_t nb = sb + (uint32_t)(((dc + 2) % 3) * BUF_STRIDE);
            cp_tile_pair(nb, T_AHI, T_ALO, Qh, Ql, D_, (dc + 2) * 32, t);
            cp_tile_pair(nb, T_BHI, T_BLO, Kh, Kl, D_, (dc + 2) * 32, t);
            CP_COMMIT();
        }
        mma_chunk32(sb + (uint32_t)((dc % 3) * BUF_STRIDE), lane, wm, wn, acc);
    }

    const int g = lane >> 2, t4 = lane & 3;
    #pragma unroll
    for (int mt = 0; mt < 4; mt++) {
        const int m = wm * 64 + mt * 16 + g;
        float* Sr0 = S + ((size_t)(b * LQ_ + qt * 128 + m)) * LK_ + (size_t)kt * 128;
        float* Sr1 = Sr0 + 8 * LK_;
        #pragma unroll
        for (int nt = 0; nt < 4; nt++) {
            const int c = wn * 32 + nt * 8 + 2 * t4;
            *(float2*)(Sr0 + c) = make_float2(acc[mt][nt][0] * INV_T, acc[mt][nt][1] * INV_T);
            *(float2*)(Sr1 + c) = make_float2(acc[mt][nt][2] * INV_T, acc[mt][nt][3] * INV_T);
        }
    }
}

// ---------------------------------------------------------------------------
// Kernel 2: per-row double softmax (mask = int32). At achieved-BW roofline.
// ---------------------------------------------------------------------------
__global__ __launch_bounds__(256) void softmax_kernel(
    float* __restrict__ S, float* __restrict__ A, const int* __restrict__ M)
{
    __shared__ float2 red[8];
    const int t = threadIdx.x;
    const size_t row = blockIdx.x;

    float4 sv = ((const float4*)(S + row * LK_))[t];
    int4  mv = ((const int4*)(M + row * LK_))[t];

    float mU = fmaxf(fmaxf(sv.x, sv.y), fmaxf(sv.z, sv.w));
    float mM = -3.0e38f;
    if (!mv.x) mM = sv.x;
    if (!mv.y) mM = fmaxf(mM, sv.y);
    if (!mv.z) mM = fmaxf(mM, sv.z);
    if (!mv.w) mM = fmaxf(mM, sv.w);

    #pragma unroll
    for (int o = 16; o > 0; o >>= 1) {
        mU = fmaxf(mU, __shfl_xor_sync(0xffffffffu, mU, o));
        mM = fmaxf(mM, __shfl_xor_sync(0xffffffffu, mM, o));
    }
    if ((t & 31) == 0) red[t >> 5] = make_float2(mU, mM);
    __syncthreads();
    #pragma unroll
    for (int w = 0; w < 8; w++) { mU = fmaxf(mU, red[w].x); mM = fmaxf(mM, red[w].y); }
    __syncthreads();

    float e0 = __expf(sv.x - mU), e1 = __expf(sv.y - mU),
          e2 = __expf(sv.z - mU), e3 = __expf(sv.w - mU);
    float sumU = (e0 + e1) + (e2 + e3);
    float f0 = mv.x ? 0.f : __expf(sv.x - mM);
    float f1 = mv.y ? 0.f : __expf(sv.y - mM);
    float f2 = mv.z ? 0.f : __expf(sv.z - mM);
    float f3 = mv.w ? 0.f : __expf(sv.w - mM);
    float sumM = (f0 + f1) + (f2 + f3);

    #pragma unroll
    for (int o = 16; o > 0; o >>= 1) {
        sumU += __shfl_xor_sync(0xffffffffu, sumU, o);
        sumM += __shfl_xor_sync(0xffffffffu, sumM, o);
    }
    if ((t & 31) == 0) red[t >> 5] = make_float2(sumU, sumM);
    __syncthreads();
    float sU = 0.f, sM = 0.f;
    #pragma unroll
    for (int w = 0; w < 8; w++) { sU += red[w].x; sM += red[w].y; }

    const float lse = mU + __logf(sU);
    const float inv = 1.0f / sM;

    ((float4*)(A + row * LK_))[t] = make_float4(f0 * inv, f1 * inv, f2 * inv, f3 * inv);
    ((float4*)(S + row * LK_))[t] =
        make_float4(sv.x - lse, sv.y - lse, sv.z - lse, sv.w - lse);
}

// ---------------------------------------------------------------------------
// Kernel 3: O = A . V. 3-stage pipeline: V at distance 2 (cp.async),
// A at distance 1 (LDG prefetch + inline split, hidden behind MMA).
// ---------------------------------------------------------------------------
__device__ __forceinline__ void store_A_split(char* smem, uint32_t bufOff,
                                              const float4* a, int t)
{
    #pragma unroll
    for (int i = 0; i < 4; i++) {
        const uint32_t u = (uint32_t)t + 256u * i;
        const uint32_t row = u >> 3, f = u & 7;
        const uint32_t dst = bufOff + swz(row, f >> 1) + (f & 1) * 8;
        __nv_bfloat16 h0,h1,h2,h3,l0,l1,l2,l3;
        split_f(a[i].x,h0,l0); split_f(a[i].y,h1,l1);
        split_f(a[i].z,h2,l2); split_f(a[i].w,h3,l3);
        *(uint2*)(smem + T_AHI + dst) = make_uint2(pk_bf2(h0,h1), pk_bf2(h2,h3));
        *(uint2*)(smem + T_ALO + dst) = make_uint2(pk_bf2(l0,l1), pk_bf2(l2,l3));
    }
}
__device__ __forceinline__ void ldg_A(const float* __restrict__ Ab, int kc, int t, float4* a)
{
    #pragma unroll
    for (int i = 0; i < 4; i++) {
        const uint32_t u = (uint32_t)t + 256u * i;
        const uint32_t row = u >> 3, f = u & 7;
        a[i] = *(const float4*)(Ab + (size_t)row * LK_ + kc * 32 + f * 4);
    }
}

__global__ __launch_bounds__(256, 2) void out_mma(
    const float* __restrict__ A, float* __restrict__ O)
{
    extern __shared__ __align__(1024) char smem[];
    const uint32_t sb = smem_u32(smem);
    const int t = threadIdx.x, lane = t & 31, wid = t >> 5;
    const int wm = wid & 1, wn = wid >> 1;

    const int qt = blockIdx.x, b = blockIdx.y;
    const float* Ab = A + ((size_t)b * LQ_ + (size_t)qt * 128) * LK_;
    const __nv_bfloat16* Vh = g_Vt_hi + (size_t)b * D_ * LK_;
    const __nv_bfloat16* Vl = g_Vt_lo + (size_t)b * D_ * LK_;

    float acc[4][4][4];
    #pragma unroll
    for (int i = 0; i < 4; i++)
        #pragma unroll
        for (int j = 0; j < 4; j++)
            #pragma unroll
            for (int g = 0; g < 4; g++) acc[i][j][g] = 0.f;

    // prologue: V chunks 0,1 -> stages 0,1; A chunk 0 -> stage 0
    {
        float4 a0[4];
        ldg_A(Ab, 0, t, a0);
        cp_tile_pair(sb, T_BHI, T_BLO, Vh, Vl, LK_, 0, t);
        CP_COMMIT();
        cp_tile_pair(sb + BUF_STRIDE, T_BHI, T_BLO, Vh, Vl, LK_, 32, t);
        CP_COMMIT();
        store_A_split(smem, 0, a0, t);
    }

    for (int kc = 0; kc < 32; kc++) {
        if (kc < 31) { CP_WAIT(1); } else { CP_WAIT(0); }
        __syncthreads();
        float4 an[4];
        if (kc + 1 < 32) ldg_A(Ab, kc + 1, t, an);          // LDG in flight
        if (kc + 2 < 32) {
            cp_tile_pair(sb + (uint32_t)(((kc + 2) % 3) * BUF_STRIDE),
                         T_BHI, T_BLO, Vh, Vl, LK_, (kc + 2) * 32, t);
            CP_COMMIT();
        }
        mma_chunk32(sb + (uint32_t)((kc % 3) * BUF_STRIDE), lane, wm, wn, acc);
        if (kc + 1 < 32)
            store_A_split(smem, (uint32_t)(((kc + 1) % 3) * BUF_STRIDE), an, t);
    }

    const int g = lane >> 2, t4 = lane & 3;
    #pragma unroll
    for (int mt = 0; mt < 4; mt++) {
        const int m = wm * 64 + mt * 16 + g;
        float* Or0 = O + ((size_t)(b * LQ_ + qt * 128 + m)) * D_;
        float* Or1 = Or0 + 8 * D_;
        #pragma unroll
        for (int nt = 0; nt < 4; nt++) {
            const int c = wn * 32 + nt * 8 + 2 * t4;
            *(float2*)(Or0 + c) = make_float2(acc[mt][nt][0], acc[mt][nt][1]);
            *(float2*)(Or1 + c) = make_float2(acc[mt][nt][2], acc[mt][nt][3]);
        }
    }
}

// ---------------------------------------------------------------------------
// Launch. Inputs: q, k, v, attn_mask (int32).
// d_out layout: output | attn | log_attn.  Raw scores staged in log_attn.
// ---------------------------------------------------------------------------
extern "C" void kernel_launch(void* const* d_in, const int* in_sizes, int n_in,
                              void* d_out, int out_size)
{
    (void)in_sizes; (void)n_in; (void)out_size;
    const float* Q = (const float*)d_in[0];
    const float* K = (const float*)d_in[1];
    const float* V = (const float*)d_in[2];
    const int*   M = (const int*)d_in[3];

    float* O   = (float*)d_out;
    float* ATT = O   + (size_t)B_ * LQ_ * D_;
    float* LA  = ATT + (size_t)B_ * LQ_ * LK_;

    __nv_bfloat16 *qh, *ql, *kh, *kl;
    cudaGetSymbolAddress((void**)&qh, g_Qhi);
    cudaGetSymbolAddress((void**)&ql, g_Qlo);
    cudaGetSymbolAddress((void**)&kh, g_Khi);
    cudaGetSymbolAddress((void**)&kl, g_Klo);

    cudaFuncSetAttribute(scores_mma, cudaFuncAttributeMaxDynamicSharedMemorySize, SM_TOTAL);
    cudaFuncSetAttribute(out_mma,    cudaFuncAttributeMaxDynamicSharedMemorySize, SM_TOTAL);

    const int n4 = B_ * LQ_ * D_ / 4;
    split2_kernel<<<dim3(n4 / 256, 2), 256>>>(Q, K, qh, ql, kh, kl);
    vtrans_kernel<<<dim3(LK_ / 32, D_ / 32, B_), dim3(32, 8)>>>(V);
    scores_mma<<<dim3(LK_ / 128, LQ_ / 128, B_), 256, SM_TOTAL>>>(LA);
    softmax_kernel<<<B_ * LQ_, 256>>>(LA, ATT, M);
    out_mma<<<dim3(LQ_ / 128, B_), 256, SM_TOTAL>>>(ATT, O);
}